// round 15
// baseline (speedup 1.0000x reference)
#include <cuda_runtime.h>
#include <cuda_bf16.h>

#define BATCH 8
#define CH    128
#define HH    112
#define WW    112
#define HWSZ  12544     // 112*112
#define NH    4
#define HD    32
#define KS    7
#define KK2   49
#define SCALE 0.17677669529663687f   // 32^-0.5

// Persistent scratch (static device allocations).
static __device__ __align__(16) __nv_bfloat16 g_wqh[3*CH*CH];        // qkv_w hi, [n][k]
static __device__ __align__(16) __nv_bfloat16 g_wql[3*CH*CH];
static __device__ __align__(16) __nv_bfloat16 g_pwh[CH*CH];          // proj_w hi
static __device__ __align__(16) __nv_bfloat16 g_pwl[CH*CH];
static __device__ __align__(16) float g_v  [BATCH*NH*HWSZ*HD];       // (b,h,p,d)
static __device__ __align__(16) float g_dot[BATCH*NH*HWSZ];          // (b,h,p)
// att hi/lo in HEAD-BLOCKED layout (b,h,p,d): attn stores coalesce.
static __device__ __align__(16) __nv_bfloat16 g_ath[BATCH*NH*HWSZ*HD];
static __device__ __align__(16) __nv_bfloat16 g_atl[BATCH*NH*HWSZ*HD];

// ---------------- helpers ----------------------------------------

__device__ __forceinline__ unsigned bfpack(__nv_bfloat16 a, __nv_bfloat16 b) {
    return (unsigned)__bfloat16_as_ushort(a) | ((unsigned)__bfloat16_as_ushort(b) << 16);
}

__device__ __forceinline__ void split4(float4 v, uint2& hi, uint2& lo) {
    __nv_bfloat16 hx = __float2bfloat16(v.x);
    __nv_bfloat16 hy = __float2bfloat16(v.y);
    __nv_bfloat16 hz = __float2bfloat16(v.z);
    __nv_bfloat16 hw = __float2bfloat16(v.w);
    __nv_bfloat16 lx = __float2bfloat16(v.x - __bfloat162float(hx));
    __nv_bfloat16 ly = __float2bfloat16(v.y - __bfloat162float(hy));
    __nv_bfloat16 lz = __float2bfloat16(v.z - __bfloat162float(hz));
    __nv_bfloat16 lw = __float2bfloat16(v.w - __bfloat162float(hw));
    hi.x = bfpack(hx, hy); hi.y = bfpack(hz, hw);
    lo.x = bfpack(lx, ly); lo.y = bfpack(lz, lw);
}

__device__ __forceinline__ void ldsm4(unsigned* r, unsigned addr) {
    asm volatile("ldmatrix.sync.aligned.m8n8.x4.shared.b16 {%0,%1,%2,%3}, [%4];"
                 : "=r"(r[0]), "=r"(r[1]), "=r"(r[2]), "=r"(r[3]) : "r"(addr));
}
__device__ __forceinline__ void ldsm4t(unsigned* r, unsigned addr) {
    asm volatile("ldmatrix.sync.aligned.m8n8.x4.trans.shared.b16 {%0,%1,%2,%3}, [%4];"
                 : "=r"(r[0]), "=r"(r[1]), "=r"(r[2]), "=r"(r[3]) : "r"(addr));
}
__device__ __forceinline__ void mma16816(float* c, const unsigned* a, const unsigned* b) {
    asm volatile(
        "mma.sync.aligned.m16n8k16.row.col.f32.bf16.bf16.f32 "
        "{%0,%1,%2,%3}, {%4,%5,%6,%7}, {%8,%9}, {%0,%1,%2,%3};"
        : "+f"(c[0]), "+f"(c[1]), "+f"(c[2]), "+f"(c[3])
        : "r"(a[0]), "r"(a[1]), "r"(a[2]), "r"(a[3]), "r"(b[0]), "r"(b[1]));
}

__device__ __forceinline__ void cpa16(unsigned dst, const void* src) {
    asm volatile("cp.async.cg.shared.global [%0], [%1], 16;" :: "r"(dst), "l"(src));
}
__device__ __forceinline__ void cpcommit() { asm volatile("cp.async.commit_group;"); }
__device__ __forceinline__ void cpwait1()  { asm volatile("cp.async.wait_group 1;"); }
__device__ __forceinline__ void cpwait0()  { asm volatile("cp.async.wait_group 0;"); }

__device__ __forceinline__ void fma2(unsigned long long& acc,
                                     unsigned long long v, unsigned long long w) {
    asm("fma.rn.f32x2 %0, %1, %2, %0;" : "+l"(acc) : "l"(v), "l"(w));
}

// ------------------------------------------------------------------
// Pre-split kernel: weights fp32 -> bf16 hi/lo (tiny)
// ------------------------------------------------------------------
__global__ __launch_bounds__(256) void split_w_kernel(
    const float* __restrict__ qw, const float* __restrict__ pw)
{
    int i = (blockIdx.x * 256 + threadIdx.x) * 4;
    uint2 hi, lo;
    if (i < 3 * CH * CH) {
        float4 v = *(const float4*)&qw[i];
        split4(v, hi, lo);
        *(uint2*)&g_wqh[i] = hi;
        *(uint2*)&g_wql[i] = lo;
    } else {
        int j = i - 3 * CH * CH;
        float4 v = *(const float4*)&pw[j];
        split4(v, hi, lo);
        *(uint2*)&g_pwh[j] = hi;
        *(uint2*)&g_pwl[j] = lo;
    }
}

// ------------------------------------------------------------------
// Kernel 1: fused QKV GEMM + q.k dot. bf16 3-term split.
// BK=64, 6 phases, 3-buffer cp.async ring. (byte-identical to R14)
// ------------------------------------------------------------------
#define QA_H 0
#define QA_L 34816
#define QB0  69632
#define QBUF 36864
#define QSM  180224    // 69632 + 3*36864

__device__ __forceinline__ void qkv_issueB(unsigned sb, int t, int p)
{
    const int nt = p >> 1, ktH = p & 1, buf = p % 3;
    const int nrow = t >> 2, c4 = t & 3;
    unsigned bd = sb + QB0 + buf * QBUF + nrow * 144 + c4 * 32;
    size_t off = (size_t)(nt * 128 + nrow) * CH + ktH * 64 + c4 * 16;
    cpa16(bd,              g_wqh + off);
    cpa16(bd + 16,         g_wqh + off + 8);
    cpa16(bd + 18432,      g_wql + off);
    cpa16(bd + 18432 + 16, g_wql + off + 8);
}

__global__ __launch_bounds__(512) void qkvdot_kernel(
    const float* __restrict__ x, const float* __restrict__ bias)
{
    extern __shared__ __align__(16) char sm[];
    const unsigned sb = (unsigned)__cvta_generic_to_shared(sm);

    const int mtile = blockIdx.x;            // 0..783
    const int b     = mtile / 98;
    const int hw0   = (mtile - b * 98) * 128;
    const int t     = threadIdx.x;
    const int l     = t & 31, w = t >> 5;
    const int wm    = w >> 2, wn = w & 3;
    const int g     = l >> 3, i = l & 7;

    // ---- prologue: B(0), B(1) via cp.async; A fp32 load + split ----
    {
        qkv_issueB(sb, t, 0);
        cpcommit();
        qkv_issueB(sb, t, 1);
        cpcommit();

        const float* xb = x + (size_t)b * (CH * HWSZ) + hw0;
        const int m4 = (t & 31) * 4;
        const int kr = t >> 5;               // 0..15
        float4 av[8];
#pragma unroll
        for (int j = 0; j < 8; ++j)
            av[j] = *(const float4*)(xb + (size_t)(kr + j * 16) * HWSZ + m4);
#pragma unroll
        for (int j = 0; j < 8; ++j) {
            uint2 hi, lo;
            split4(av[j], hi, lo);
            unsigned ad = sb + QA_H + (kr + j * 16) * 272 + m4 * 2;
            *(uint2*)__cvta_shared_to_generic(ad) = hi;
            *(uint2*)__cvta_shared_to_generic(ad + (QA_L - QA_H)) = lo;
        }
        cpwait1();
        __syncthreads();
    }

    float c[2][4][4];
    float qreg[2][4][4];
#pragma unroll
    for (int mf = 0; mf < 2; ++mf)
#pragma unroll
        for (int nf = 0; nf < 4; ++nf)
#pragma unroll
            for (int r2 = 0; r2 < 4; ++r2) c[mf][nf][r2] = 0.f;

    for (int p = 0; p < 6; ++p) {
        const int nt = p >> 1, ktH = p & 1, buf = p % 3;

        if (p < 4) { qkv_issueB(sb, t, p + 2); cpcommit(); }

        const unsigned Bb = sb + QB0 + buf * QBUF;
#pragma unroll
        for (int kb = 0; kb < 64; kb += 16) {
            unsigned ah[2][4], al_[2][4], bh[4][2], bl[4][2];
#pragma unroll
            for (int mf = 0; mf < 2; ++mf) {
                int row  = ktH * 64 + kb + i + ((g >> 1) << 3);
                int mcol = wm * 32 + mf * 16 + ((g & 1) << 3);
                unsigned ad = sb + QA_H + row * 272 + mcol * 2;
                ldsm4t(ah[mf], ad);
                ldsm4t(al_[mf], ad + (QA_L - QA_H));
            }
#pragma unroll
            for (int ng = 0; ng < 2; ++ng) {
                int nrow = wn * 32 + ng * 16 + ((g >> 1) << 3) + i;
                unsigned bd = Bb + nrow * 144 + kb * 2 + ((g & 1) << 4);
                unsigned r[4];
                ldsm4(r, bd);
                bh[ng * 2][0] = r[0]; bh[ng * 2][1] = r[1];
                bh[ng * 2 + 1][0] = r[2]; bh[ng * 2 + 1][1] = r[3];
                ldsm4(r, bd + 18432);
                bl[ng * 2][0] = r[0]; bl[ng * 2][1] = r[1];
                bl[ng * 2 + 1][0] = r[2]; bl[ng * 2 + 1][1] = r[3];
            }
#pragma unroll
            for (int mf = 0; mf < 2; ++mf)
#pragma unroll
                for (int nf = 0; nf < 4; ++nf) {
                    mma16816(c[mf][nf], ah[mf], bh[nf]);
                    mma16816(c[mf][nf], ah[mf], bl[nf]);
                    mma16816(c[mf][nf], al_[mf], bh[nf]);
                }
        }

        if (ktH == 1) {
            if (nt == 0) {
#pragma unroll
                for (int mf = 0; mf < 2; ++mf)
#pragma unroll
                    for (int nf = 0; nf < 4; ++nf) {
                        int n = wn * 32 + nf * 8 + (l & 3) * 2;
                        float b0 = bias[n], b1 = bias[n + 1];
                        qreg[mf][nf][0] = c[mf][nf][0] + b0;
                        qreg[mf][nf][1] = c[mf][nf][1] + b1;
                        qreg[mf][nf][2] = c[mf][nf][2] + b0;
                        qreg[mf][nf][3] = c[mf][nf][3] + b1;
                    }
            } else if (nt == 1) {
#pragma unroll
                for (int mf = 0; mf < 2; ++mf) {
                    float s0 = 0.f, s1 = 0.f;
                    int m = wm * 32 + mf * 16 + (l >> 2);
#pragma unroll
                    for (int nf = 0; nf < 4; ++nf) {
                        int n = wn * 32 + nf * 8 + (l & 3) * 2;
                        float b0 = bias[128 + n], b1 = bias[128 + n + 1];
                        s0 += qreg[mf][nf][0] * (c[mf][nf][0] + b0)
                            + qreg[mf][nf][1] * (c[mf][nf][1] + b1);
                        s1 += qreg[mf][nf][2] * (c[mf][nf][2] + b0)
                            + qreg[mf][nf][3] * (c[mf][nf][3] + b1);
                    }
                    s0 += __shfl_xor_sync(0xffffffffu, s0, 1);
                    s0 += __shfl_xor_sync(0xffffffffu, s0, 2);
                    s1 += __shfl_xor_sync(0xffffffffu, s1, 1);
                    s1 += __shfl_xor_sync(0xffffffffu, s1, 2);
                    if ((l & 3) == 0) {
                        size_t base = (size_t)(b * NH + wn) * HWSZ + hw0;
                        g_dot[base + m]     = s0 * SCALE;
                        g_dot[base + m + 8] = s1 * SCALE;
                    }
                }
            } else {
#pragma unroll
                for (int mf = 0; mf < 2; ++mf)
#pragma unroll
                    for (int nf = 0; nf < 4; ++nf) {
                        int n = wn * 32 + nf * 8 + (l & 3) * 2;
                        int m = wm * 32 + mf * 16 + (l >> 2);
                        float b0 = bias[256 + n], b1 = bias[256 + n + 1];
                        int d = n & 31;
                        float* hb = g_v + ((size_t)(b * NH + wn) * HWSZ + hw0) * HD + d;
                        *(float2*)&hb[(size_t)m * HD] =
                            make_float2(c[mf][nf][0] + b0, c[mf][nf][1] + b1);
                        *(float2*)&hb[(size_t)(m + 8) * HD] =
                            make_float2(c[mf][nf][2] + b0, c[mf][nf][3] + b1);
                    }
            }
#pragma unroll
            for (int mf = 0; mf < 2; ++mf)
#pragma unroll
                for (int nf = 0; nf < 4; ++nf)
#pragma unroll
                    for (int r2 = 0; r2 < 4; ++r2) c[mf][nf][r2] = 0.f;
        }

        if (p < 4)       cpwait1();
        else if (p == 4) cpwait0();
        __syncthreads();
    }
}

// ------------------------------------------------------------------
// Kernel 2: neighborhood attention (circular), vertical 2-px strip.
// R11 structure; accumulate via fma.rn.f32x2 (halves FMA issue count;
// element-wise rounding identical to two fmaf -> same numerics).
// ------------------------------------------------------------------
__global__ __launch_bounds__(128) void attn_kernel(const float* __restrict__ rpb)
{
    __shared__ __align__(16) float ds[22 * 24];
    __shared__ __align__(16) float rs[KK2];
    __shared__ __align__(16) float vs[484 * 20];

    const int bh = blockIdx.z;        // b*4 + h
    const int h  = bh & 3;
    const int b  = bh >> 2;
    const int y0 = blockIdx.y * 16;
    const int x0 = blockIdx.x * 16;
    const int tid = threadIdx.x;

    for (int idx = tid; idx < 484; idx += 128) {
        int r  = idx / 22, cc = idx - r * 22;
        int gy = y0 + r;  if (gy >= HH) gy -= HH;
        int gx = x0 + cc; if (gx >= WW) gx -= WW;
        ds[r * 24 + cc] = g_dot[(size_t)bh * HWSZ + gy * WW + gx];
    }
    if (tid < KK2) rs[tid] = rpb[h * KK2 + tid];

    const float* vbase = g_v + (size_t)bh * (HWSZ * HD);

    for (int idx = tid; idx < 484 * 4; idx += 128) {
        int pix = idx >> 2, gg = idx & 3;
        int r  = pix / 22, cc = pix - r * 22;
        int gy = y0 + r;  if (gy >= HH) gy -= HH;
        int gx = x0 + cc; if (gx >= WW) gx -= WW;
        *(float4*)&vs[pix * 20 + gg * 4] =
            *(const float4*)&vbase[(size_t)(gy * WW + gx) * HD + gg * 4];
    }
    __syncthreads();

    const int ty2 = tid >> 4;          // 0..7 -> rows 2*ty2, 2*ty2+1
    const int tx  = tid & 15;

    float wgt[2][KK2];
#pragma unroll
    for (int px = 0; px < 2; ++px) {
        float mx = -1e30f;
#pragma unroll
        for (int i = 0; i < 7; ++i)
#pragma unroll
            for (int j = 0; j < 7; ++j) {
                float val = ds[(2 * ty2 + px + i) * 24 + tx + j] + rs[i * 7 + j];
                wgt[px][i * 7 + j] = val;
                mx = fmaxf(mx, val);
            }
        float sum = 0.f;
#pragma unroll
        for (int n = 0; n < KK2; ++n) { wgt[px][n] = __expf(wgt[px][n] - mx); sum += wgt[px][n]; }
        float inv = 1.f / sum;
#pragma unroll
        for (int n = 0; n < KK2; ++n) wgt[px][n] *= inv;
    }

    const int p0 = (y0 + 2 * ty2) * WW + (x0 + tx);
    const size_t ob0 = ((size_t)(b * NH + h) * HWSZ + p0) * HD;
    const size_t ob1 = ob0 + (size_t)WW * HD;

#pragma unroll
    for (int half = 0; half < 2; ++half) {
        if (half == 1) {
            __syncthreads();
            for (int idx = tid; idx < 484 * 4; idx += 128) {
                int pix = idx >> 2, gg = idx & 3;
                int r  = pix / 22, cc = pix - r * 22;
                int gy = y0 + r;  if (gy >= HH) gy -= HH;
                int gx = x0 + cc; if (gx >= WW) gx -= WW;
                *(float4*)&vs[pix * 20 + gg * 4] =
                    *(const float4*)&vbase[(size_t)(gy * WW + gx) * HD + 16 + gg * 4];
            }
            __syncthreads();
        }

        // packed accumulators: 16 channels = 8 f32x2 per pixel
        unsigned long long a0[8], a1[8];
#pragma unroll
        for (int e = 0; e < 8; ++e) { a0[e] = 0ULL; a1[e] = 0ULL; }

#pragma unroll
        for (int i = 0; i < 8; ++i)
#pragma unroll
            for (int j = 0; j < 7; ++j) {
                int pix = (2 * ty2 + i) * 22 + (tx + j);
                const ulonglong2* vp = (const ulonglong2*)&vs[pix * 20];
                ulonglong2 va = vp[0];   // ch 0-3
                ulonglong2 vb = vp[1];   // ch 4-7
                ulonglong2 vc = vp[2];   // ch 8-11
                ulonglong2 vd = vp[3];   // ch 12-15
                if (i < 7) {
                    unsigned long long w0p;
                    float w0 = wgt[0][i * 7 + j];
                    asm("mov.b64 %0, {%1, %1};" : "=l"(w0p) : "f"(w0));
                    fma2(a0[0], va.x, w0p); fma2(a0[1], va.y, w0p);
                    fma2(a0[2], vb.x, w0p); fma2(a0[3], vb.y, w0p);
                    fma2(a0[4], vc.x, w0p); fma2(a0[5], vc.y, w0p);
                    fma2(a0[6], vd.x, w0p); fma2(a0[7], vd.y, w0p);
                }
                if (i >= 1) {
                    unsigned long long w1p;
                    float w1 = wgt[1][(i - 1) * 7 + j];
                    asm("mov.b64 %0, {%1, %1};" : "=l"(w1p) : "f"(w1));
                    fma2(a1[0], va.x, w1p); fma2(a1[1], va.y, w1p);
                    fma2(a1[2], vb.x, w1p); fma2(a1[3], vb.y, w1p);
                    fma2(a1[4], vc.x, w1p); fma2(a1[5], vc.y, w1p);
                    fma2(a1[6], vd.x, w1p); fma2(a1[7], vd.y, w1p);
                }
            }

        // store both pixels, this half (16 channels each)
#pragma unroll
        for (int px = 0; px < 2; ++px) {
            unsigned long long* acc = px ? a1 : a0;
            unsigned hi_u[8], lo_u[8];
#pragma unroll
            for (int e = 0; e < 8; ++e) {
                float f0, f1;
                asm("mov.b64 {%0, %1}, %2;" : "=f"(f0), "=f"(f1) : "l"(acc[e]));
                __nv_bfloat16 h0 = __float2bfloat16(f0);
                __nv_bfloat16 h1 = __float2bfloat16(f1);
                __nv_bfloat16 l0 = __float2bfloat16(f0 - __bfloat162float(h0));
                __nv_bfloat16 l1 = __float2bfloat16(f1 - __bfloat162float(h1));
                hi_u[e] = bfpack(h0, h1);
                lo_u[e] = bfpack(l0, l1);
            }
            size_t ob = (px ? ob1 : ob0) + half * 16;
            *(uint4*)&g_ath[ob]     = make_uint4(hi_u[0], hi_u[1], hi_u[2], hi_u[3]);
            *(uint4*)&g_ath[ob + 8] = make_uint4(hi_u[4], hi_u[5], hi_u[6], hi_u[7]);
            *(uint4*)&g_atl[ob]     = make_uint4(lo_u[0], lo_u[1], lo_u[2], lo_u[3]);
            *(uint4*)&g_atl[ob + 8] = make_uint4(lo_u[4], lo_u[5], lo_u[6], lo_u[7]);
        }
    }
}

// ------------------------------------------------------------------
// Kernel 3: proj GEMM. (byte-identical to R14, 44.8us)
// ------------------------------------------------------------------
#define PBUF 40960
#define PSM  122880    // 3*40960

__device__ __forceinline__ void proj_issue(unsigned sb, int t, int bq, int hw0, int kt)
{
    const unsigned base = sb + (kt % 3) * PBUF;
    const int mrow = t >> 2, c4 = t & 3;
    unsigned ad = base + mrow * 80 + c4 * 16;
    size_t aoff = ((size_t)(bq * NH + kt) * HWSZ + hw0 + mrow) * HD + c4 * 8;
    cpa16(ad,         g_ath + aoff);
    cpa16(ad + 10240, g_atl + aoff);
    unsigned bd = base + 20480 + mrow * 80 + c4 * 16;
    size_t boff = (size_t)mrow * CH + kt * 32 + c4 * 8;
    cpa16(bd,         g_pwh + boff);
    cpa16(bd + 10240, g_pwl + boff);
}

__global__ __launch_bounds__(512) void proj_kernel(
    const float* __restrict__ pb, float* __restrict__ out)
{
    extern __shared__ __align__(16) char sm[];
    const unsigned sb = (unsigned)__cvta_generic_to_shared(sm);

    const int mtile = blockIdx.x;
    const int bq    = mtile / 98;
    const int hw0   = (mtile - bq * 98) * 128;
    const int t     = threadIdx.x;
    const int l     = t & 31, w = t >> 5;
    const int wm    = w >> 2, wn = w & 3;
    const int g     = l >> 3, i = l & 7;

    {
        proj_issue(sb, t, bq, hw0, 0);
        cpcommit();
        proj_issue(sb, t, bq, hw0, 1);
        cpcommit();
        cpwait1();
        __syncthreads();
    }

    float c[2][4][4];
#pragma unroll
    for (int mf = 0; mf < 2; ++mf)
#pragma unroll
        for (int nf = 0; nf < 4; ++nf)
#pragma unroll
            for (int r2 = 0; r2 < 4; ++r2) c[mf][nf][r2] = 0.f;

    for (int kt = 0; kt < 4; ++kt) {
        const unsigned Cb = sb + (kt % 3) * PBUF;
        if (kt < 2) { proj_issue(sb, t, bq, hw0, kt + 2); cpcommit(); }

#pragma unroll
        for (int kb = 0; kb < 32; kb += 16) {
            unsigned ah[2][4], al_[2][4], bh[4][2], bl[4][2];
#pragma unroll
            for (int mf = 0; mf < 2; ++mf) {
                int mrow = wm * 32 + mf * 16 + ((g & 1) << 3) + i;
                unsigned ad = Cb + mrow * 80 + kb * 2 + ((g >> 1) << 4);
                ldsm4(ah[mf], ad);
                ldsm4(al_[mf], ad + 10240);
            }
#pragma unroll
            for (int ng = 0; ng < 2; ++ng) {
                int nrow = wn * 32 + ng * 16 + ((g >> 1) << 3) + i;
                unsigned bd = Cb + 20480 + nrow * 80 + kb * 2 + ((g & 1) << 4);
                unsigned r[4];
                ldsm4(r, bd);
                bh[ng * 2][0] = r[0]; bh[ng * 2][1] = r[1];
                bh[ng * 2 + 1][0] = r[2]; bh[ng * 2 + 1][1] = r[3];
                ldsm4(r, bd + 10240);
                bl[ng * 2][0] = r[0]; bl[ng * 2][1] = r[1];
                bl[ng * 2 + 1][0] = r[2]; bl[ng * 2 + 1][1] = r[3];
            }
#pragma unroll
            for (int mf = 0; mf < 2; ++mf)
#pragma unroll
                for (int nf = 0; nf < 4; ++nf) {
                    mma16816(c[mf][nf], ah[mf], bh[nf]);
                    mma16816(c[mf][nf], ah[mf], bl[nf]);
                    mma16816(c[mf][nf], al_[mf], bh[nf]);
                }
        }
        if (kt < 2)       cpwait1();
        else if (kt == 2) cpwait0();
        __syncthreads();
    }

    // ---- direct STG epilogue: out[bq, n, hw0 + m] = c + pb[n] ----
#pragma unroll
    for (int mf = 0; mf < 2; ++mf)
#pragma unroll
        for (int nf = 0; nf < 4; ++nf) {
            int n = wn * 32 + nf * 8 + (l & 3) * 2;
            int m = wm * 32 + mf * 16 + (l >> 2);
            float b0 = pb[n], b1 = pb[n + 1];
            float* r0 = out + (size_t)(bq * CH + n) * HWSZ + hw0;
            float* r1 = out + (size_t)(bq * CH + n + 1) * HWSZ + hw0;
            r0[m]     = c[mf][nf][0] + b0;
            r1[m]     = c[mf][nf][1] + b1;
            r0[m + 8] = c[mf][nf][2] + b0;
            r1[m + 8] = c[mf][nf][3] + b1;
        }
}

// ------------------------------------------------------------------
extern "C" void kernel_launch(void* const* d_in, const int* in_sizes, int n_in,
                              void* d_out, int out_size)
{
    const float* x      = (const float*)d_in[0];
    const float* qkv_w  = (const float*)d_in[1];
    const float* qkv_b  = (const float*)d_in[2];
    const float* rpb    = (const float*)d_in[3];
    const float* proj_w = (const float*)d_in[4];
    const float* proj_b = (const float*)d_in[5];
    float* out = (float*)d_out;

    cudaFuncSetAttribute(qkvdot_kernel,
                         cudaFuncAttributeMaxDynamicSharedMemorySize, QSM);
    cudaFuncSetAttribute(proj_kernel,
                         cudaFuncAttributeMaxDynamicSharedMemorySize, PSM);

    split_w_kernel<<<(3 * CH * CH + CH * CH) / 1024, 256>>>(qkv_w, proj_w);
    qkvdot_kernel<<<784, 512, QSM>>>(x, qkv_b);
    attn_kernel<<<dim3(7, 7, 32), 128>>>(rpb);
    proj_kernel<<<784, 512, PSM>>>(proj_b, out);
}

// round 16
// speedup vs baseline: 1.0753x; 1.0753x over previous
#include <cuda_runtime.h>
#include <cuda_bf16.h>

#define BATCH 8
#define CH    128
#define HH    112
#define WW    112
#define HWSZ  12544     // 112*112
#define NH    4
#define HD    32
#define KS    7
#define KK2   49
#define SCALE 0.17677669529663687f   // 32^-0.5

// Persistent scratch (static device allocations).
static __device__ __align__(16) __nv_bfloat16 g_wqh[3*CH*CH];        // qkv_w hi, [n][k]
static __device__ __align__(16) __nv_bfloat16 g_wql[3*CH*CH];
static __device__ __align__(16) __nv_bfloat16 g_pwh[CH*CH];          // proj_w hi
static __device__ __align__(16) __nv_bfloat16 g_pwl[CH*CH];
static __device__ __align__(16) float g_v  [BATCH*NH*HWSZ*HD];       // (b,h,p,d)
static __device__ __align__(16) float g_dot[BATCH*NH*HWSZ];          // (b,h,p)
// att hi/lo in HEAD-BLOCKED layout (b,h,p,d): attn stores coalesce.
static __device__ __align__(16) __nv_bfloat16 g_ath[BATCH*NH*HWSZ*HD];
static __device__ __align__(16) __nv_bfloat16 g_atl[BATCH*NH*HWSZ*HD];

// ---------------- helpers ----------------------------------------

__device__ __forceinline__ unsigned bfpack(__nv_bfloat16 a, __nv_bfloat16 b) {
    return (unsigned)__bfloat16_as_ushort(a) | ((unsigned)__bfloat16_as_ushort(b) << 16);
}

__device__ __forceinline__ void split4(float4 v, uint2& hi, uint2& lo) {
    __nv_bfloat16 hx = __float2bfloat16(v.x);
    __nv_bfloat16 hy = __float2bfloat16(v.y);
    __nv_bfloat16 hz = __float2bfloat16(v.z);
    __nv_bfloat16 hw = __float2bfloat16(v.w);
    __nv_bfloat16 lx = __float2bfloat16(v.x - __bfloat162float(hx));
    __nv_bfloat16 ly = __float2bfloat16(v.y - __bfloat162float(hy));
    __nv_bfloat16 lz = __float2bfloat16(v.z - __bfloat162float(hz));
    __nv_bfloat16 lw = __float2bfloat16(v.w - __bfloat162float(hw));
    hi.x = bfpack(hx, hy); hi.y = bfpack(hz, hw);
    lo.x = bfpack(lx, ly); lo.y = bfpack(lz, lw);
}

__device__ __forceinline__ void ldsm4(unsigned* r, unsigned addr) {
    asm volatile("ldmatrix.sync.aligned.m8n8.x4.shared.b16 {%0,%1,%2,%3}, [%4];"
                 : "=r"(r[0]), "=r"(r[1]), "=r"(r[2]), "=r"(r[3]) : "r"(addr));
}
__device__ __forceinline__ void ldsm4t(unsigned* r, unsigned addr) {
    asm volatile("ldmatrix.sync.aligned.m8n8.x4.trans.shared.b16 {%0,%1,%2,%3}, [%4];"
                 : "=r"(r[0]), "=r"(r[1]), "=r"(r[2]), "=r"(r[3]) : "r"(addr));
}
__device__ __forceinline__ void mma16816(float* c, const unsigned* a, const unsigned* b) {
    asm volatile(
        "mma.sync.aligned.m16n8k16.row.col.f32.bf16.bf16.f32 "
        "{%0,%1,%2,%3}, {%4,%5,%6,%7}, {%8,%9}, {%0,%1,%2,%3};"
        : "+f"(c[0]), "+f"(c[1]), "+f"(c[2]), "+f"(c[3])
        : "r"(a[0]), "r"(a[1]), "r"(a[2]), "r"(a[3]), "r"(b[0]), "r"(b[1]));
}

__device__ __forceinline__ void cpa16(unsigned dst, const void* src) {
    asm volatile("cp.async.cg.shared.global [%0], [%1], 16;" :: "r"(dst), "l"(src));
}
__device__ __forceinline__ void cpcommit() { asm volatile("cp.async.commit_group;"); }
__device__ __forceinline__ void cpwait1()  { asm volatile("cp.async.wait_group 1;"); }
__device__ __forceinline__ void cpwait0()  { asm volatile("cp.async.wait_group 0;"); }

// ------------------------------------------------------------------
// Pre-split kernel: weights fp32 -> bf16 hi/lo (tiny)
// ------------------------------------------------------------------
__global__ __launch_bounds__(256) void split_w_kernel(
    const float* __restrict__ qw, const float* __restrict__ pw)
{
    int i = (blockIdx.x * 256 + threadIdx.x) * 4;
    uint2 hi, lo;
    if (i < 3 * CH * CH) {
        float4 v = *(const float4*)&qw[i];
        split4(v, hi, lo);
        *(uint2*)&g_wqh[i] = hi;
        *(uint2*)&g_wql[i] = lo;
    } else {
        int j = i - 3 * CH * CH;
        float4 v = *(const float4*)&pw[j];
        split4(v, hi, lo);
        *(uint2*)&g_pwh[j] = hi;
        *(uint2*)&g_pwl[j] = lo;
    }
}

// ------------------------------------------------------------------
// Kernel 1: fused QKV GEMM + q.k dot. bf16 3-term split.
// BK=64, 6 phases, 3-buffer cp.async ring. (R14 champion)
// ------------------------------------------------------------------
#define QA_H 0
#define QA_L 34816
#define QB0  69632
#define QBUF 36864
#define QSM  180224    // 69632 + 3*36864

__device__ __forceinline__ void qkv_issueB(unsigned sb, int t, int p)
{
    const int nt = p >> 1, ktH = p & 1, buf = p % 3;
    const int nrow = t >> 2, c4 = t & 3;
    unsigned bd = sb + QB0 + buf * QBUF + nrow * 144 + c4 * 32;
    size_t off = (size_t)(nt * 128 + nrow) * CH + ktH * 64 + c4 * 16;
    cpa16(bd,              g_wqh + off);
    cpa16(bd + 16,         g_wqh + off + 8);
    cpa16(bd + 18432,      g_wql + off);
    cpa16(bd + 18432 + 16, g_wql + off + 8);
}

__global__ __launch_bounds__(512) void qkvdot_kernel(
    const float* __restrict__ x, const float* __restrict__ bias)
{
    extern __shared__ __align__(16) char sm[];
    const unsigned sb = (unsigned)__cvta_generic_to_shared(sm);

    const int mtile = blockIdx.x;            // 0..783
    const int b     = mtile / 98;
    const int hw0   = (mtile - b * 98) * 128;
    const int t     = threadIdx.x;
    const int l     = t & 31, w = t >> 5;
    const int wm    = w >> 2, wn = w & 3;
    const int g     = l >> 3, i = l & 7;

    // ---- prologue: B(0), B(1) via cp.async; A fp32 load + split ----
    {
        qkv_issueB(sb, t, 0);
        cpcommit();
        qkv_issueB(sb, t, 1);
        cpcommit();

        const float* xb = x + (size_t)b * (CH * HWSZ) + hw0;
        const int m4 = (t & 31) * 4;
        const int kr = t >> 5;               // 0..15
        float4 av[8];
#pragma unroll
        for (int j = 0; j < 8; ++j)
            av[j] = *(const float4*)(xb + (size_t)(kr + j * 16) * HWSZ + m4);
#pragma unroll
        for (int j = 0; j < 8; ++j) {
            uint2 hi, lo;
            split4(av[j], hi, lo);
            unsigned ad = sb + QA_H + (kr + j * 16) * 272 + m4 * 2;
            *(uint2*)__cvta_shared_to_generic(ad) = hi;
            *(uint2*)__cvta_shared_to_generic(ad + (QA_L - QA_H)) = lo;
        }
        cpwait1();
        __syncthreads();
    }

    float c[2][4][4];
    float qreg[2][4][4];
#pragma unroll
    for (int mf = 0; mf < 2; ++mf)
#pragma unroll
        for (int nf = 0; nf < 4; ++nf)
#pragma unroll
            for (int r2 = 0; r2 < 4; ++r2) c[mf][nf][r2] = 0.f;

    for (int p = 0; p < 6; ++p) {
        const int nt = p >> 1, ktH = p & 1, buf = p % 3;

        if (p < 4) { qkv_issueB(sb, t, p + 2); cpcommit(); }

        const unsigned Bb = sb + QB0 + buf * QBUF;
#pragma unroll
        for (int kb = 0; kb < 64; kb += 16) {
            unsigned ah[2][4], al_[2][4], bh[4][2], bl[4][2];
#pragma unroll
            for (int mf = 0; mf < 2; ++mf) {
                int row  = ktH * 64 + kb + i + ((g >> 1) << 3);
                int mcol = wm * 32 + mf * 16 + ((g & 1) << 3);
                unsigned ad = sb + QA_H + row * 272 + mcol * 2;
                ldsm4t(ah[mf], ad);
                ldsm4t(al_[mf], ad + (QA_L - QA_H));
            }
#pragma unroll
            for (int ng = 0; ng < 2; ++ng) {
                int nrow = wn * 32 + ng * 16 + ((g >> 1) << 3) + i;
                unsigned bd = Bb + nrow * 144 + kb * 2 + ((g & 1) << 4);
                unsigned r[4];
                ldsm4(r, bd);
                bh[ng * 2][0] = r[0]; bh[ng * 2][1] = r[1];
                bh[ng * 2 + 1][0] = r[2]; bh[ng * 2 + 1][1] = r[3];
                ldsm4(r, bd + 18432);
                bl[ng * 2][0] = r[0]; bl[ng * 2][1] = r[1];
                bl[ng * 2 + 1][0] = r[2]; bl[ng * 2 + 1][1] = r[3];
            }
#pragma unroll
            for (int mf = 0; mf < 2; ++mf)
#pragma unroll
                for (int nf = 0; nf < 4; ++nf) {
                    mma16816(c[mf][nf], ah[mf], bh[nf]);
                    mma16816(c[mf][nf], ah[mf], bl[nf]);
                    mma16816(c[mf][nf], al_[mf], bh[nf]);
                }
        }

        if (ktH == 1) {
            if (nt == 0) {
#pragma unroll
                for (int mf = 0; mf < 2; ++mf)
#pragma unroll
                    for (int nf = 0; nf < 4; ++nf) {
                        int n = wn * 32 + nf * 8 + (l & 3) * 2;
                        float b0 = bias[n], b1 = bias[n + 1];
                        qreg[mf][nf][0] = c[mf][nf][0] + b0;
                        qreg[mf][nf][1] = c[mf][nf][1] + b1;
                        qreg[mf][nf][2] = c[mf][nf][2] + b0;
                        qreg[mf][nf][3] = c[mf][nf][3] + b1;
                    }
            } else if (nt == 1) {
#pragma unroll
                for (int mf = 0; mf < 2; ++mf) {
                    float s0 = 0.f, s1 = 0.f;
                    int m = wm * 32 + mf * 16 + (l >> 2);
#pragma unroll
                    for (int nf = 0; nf < 4; ++nf) {
                        int n = wn * 32 + nf * 8 + (l & 3) * 2;
                        float b0 = bias[128 + n], b1 = bias[128 + n + 1];
                        s0 += qreg[mf][nf][0] * (c[mf][nf][0] + b0)
                            + qreg[mf][nf][1] * (c[mf][nf][1] + b1);
                        s1 += qreg[mf][nf][2] * (c[mf][nf][2] + b0)
                            + qreg[mf][nf][3] * (c[mf][nf][3] + b1);
                    }
                    s0 += __shfl_xor_sync(0xffffffffu, s0, 1);
                    s0 += __shfl_xor_sync(0xffffffffu, s0, 2);
                    s1 += __shfl_xor_sync(0xffffffffu, s1, 1);
                    s1 += __shfl_xor_sync(0xffffffffu, s1, 2);
                    if ((l & 3) == 0) {
                        size_t base = (size_t)(b * NH + wn) * HWSZ + hw0;
                        g_dot[base + m]     = s0 * SCALE;
                        g_dot[base + m + 8] = s1 * SCALE;
                    }
                }
            } else {
#pragma unroll
                for (int mf = 0; mf < 2; ++mf)
#pragma unroll
                    for (int nf = 0; nf < 4; ++nf) {
                        int n = wn * 32 + nf * 8 + (l & 3) * 2;
                        int m = wm * 32 + mf * 16 + (l >> 2);
                        float b0 = bias[256 + n], b1 = bias[256 + n + 1];
                        int d = n & 31;
                        float* hb = g_v + ((size_t)(b * NH + wn) * HWSZ + hw0) * HD + d;
                        *(float2*)&hb[(size_t)m * HD] =
                            make_float2(c[mf][nf][0] + b0, c[mf][nf][1] + b1);
                        *(float2*)&hb[(size_t)(m + 8) * HD] =
                            make_float2(c[mf][nf][2] + b0, c[mf][nf][3] + b1);
                    }
            }
#pragma unroll
            for (int mf = 0; mf < 2; ++mf)
#pragma unroll
                for (int nf = 0; nf < 4; ++nf)
#pragma unroll
                    for (int r2 = 0; r2 < 4; ++r2) c[mf][nf][r2] = 0.f;
        }

        if (p < 4)       cpwait1();
        else if (p == 4) cpwait0();
        __syncthreads();
    }
}

// ------------------------------------------------------------------
// Kernel 2: neighborhood attention (circular), vertical 2-px strip.
// (R11/R14 champion — scalar FFMA; f32x2 disproven twice)
// ------------------------------------------------------------------
__global__ __launch_bounds__(128) void attn_kernel(const float* __restrict__ rpb)
{
    __shared__ __align__(16) float ds[22 * 24];
    __shared__ __align__(16) float rs[KK2];
    __shared__ __align__(16) float vs[484 * 20];

    const int bh = blockIdx.z;        // b*4 + h
    const int h  = bh & 3;
    const int b  = bh >> 2;
    const int y0 = blockIdx.y * 16;
    const int x0 = blockIdx.x * 16;
    const int tid = threadIdx.x;

    for (int idx = tid; idx < 484; idx += 128) {
        int r  = idx / 22, cc = idx - r * 22;
        int gy = y0 + r;  if (gy >= HH) gy -= HH;
        int gx = x0 + cc; if (gx >= WW) gx -= WW;
        ds[r * 24 + cc] = g_dot[(size_t)bh * HWSZ + gy * WW + gx];
    }
    if (tid < KK2) rs[tid] = rpb[h * KK2 + tid];

    const float* vbase = g_v + (size_t)bh * (HWSZ * HD);

    for (int idx = tid; idx < 484 * 4; idx += 128) {
        int pix = idx >> 2, gg = idx & 3;
        int r  = pix / 22, cc = pix - r * 22;
        int gy = y0 + r;  if (gy >= HH) gy -= HH;
        int gx = x0 + cc; if (gx >= WW) gx -= WW;
        *(float4*)&vs[pix * 20 + gg * 4] =
            *(const float4*)&vbase[(size_t)(gy * WW + gx) * HD + gg * 4];
    }
    __syncthreads();

    const int ty2 = tid >> 4;          // 0..7 -> rows 2*ty2, 2*ty2+1
    const int tx  = tid & 15;

    float wgt[2][KK2];
#pragma unroll
    for (int px = 0; px < 2; ++px) {
        float mx = -1e30f;
#pragma unroll
        for (int i = 0; i < 7; ++i)
#pragma unroll
            for (int j = 0; j < 7; ++j) {
                float val = ds[(2 * ty2 + px + i) * 24 + tx + j] + rs[i * 7 + j];
                wgt[px][i * 7 + j] = val;
                mx = fmaxf(mx, val);
            }
        float sum = 0.f;
#pragma unroll
        for (int n = 0; n < KK2; ++n) { wgt[px][n] = __expf(wgt[px][n] - mx); sum += wgt[px][n]; }
        float inv = 1.f / sum;
#pragma unroll
        for (int n = 0; n < KK2; ++n) wgt[px][n] *= inv;
    }

    const int p0 = (y0 + 2 * ty2) * WW + (x0 + tx);
    const size_t ob0 = ((size_t)(b * NH + h) * HWSZ + p0) * HD;
    const size_t ob1 = ob0 + (size_t)WW * HD;

#pragma unroll
    for (int half = 0; half < 2; ++half) {
        if (half == 1) {
            __syncthreads();
            for (int idx = tid; idx < 484 * 4; idx += 128) {
                int pix = idx >> 2, gg = idx & 3;
                int r  = pix / 22, cc = pix - r * 22;
                int gy = y0 + r;  if (gy >= HH) gy -= HH;
                int gx = x0 + cc; if (gx >= WW) gx -= WW;
                *(float4*)&vs[pix * 20 + gg * 4] =
                    *(const float4*)&vbase[(size_t)(gy * WW + gx) * HD + 16 + gg * 4];
            }
            __syncthreads();
        }

        float4 acc0[4], acc1[4];
#pragma unroll
        for (int gg = 0; gg < 4; ++gg) {
            acc0[gg] = make_float4(0.f, 0.f, 0.f, 0.f);
            acc1[gg] = make_float4(0.f, 0.f, 0.f, 0.f);
        }
#pragma unroll
        for (int i = 0; i < 8; ++i)
#pragma unroll
            for (int j = 0; j < 7; ++j) {
                int pix = (2 * ty2 + i) * 22 + (tx + j);
                float w0 = (i < 7) ? wgt[0][i * 7 + j] : 0.f;
                float w1 = (i >= 1) ? wgt[1][(i - 1) * 7 + j] : 0.f;
#pragma unroll
                for (int gg = 0; gg < 4; ++gg) {
                    float4 vv = *(const float4*)&vs[pix * 20 + gg * 4];
                    if (i < 7) {
                        acc0[gg].x = fmaf(w0, vv.x, acc0[gg].x);
                        acc0[gg].y = fmaf(w0, vv.y, acc0[gg].y);
                        acc0[gg].z = fmaf(w0, vv.z, acc0[gg].z);
                        acc0[gg].w = fmaf(w0, vv.w, acc0[gg].w);
                    }
                    if (i >= 1) {
                        acc1[gg].x = fmaf(w1, vv.x, acc1[gg].x);
                        acc1[gg].y = fmaf(w1, vv.y, acc1[gg].y);
                        acc1[gg].z = fmaf(w1, vv.z, acc1[gg].z);
                        acc1[gg].w = fmaf(w1, vv.w, acc1[gg].w);
                    }
                }
            }

#pragma unroll
        for (int px = 0; px < 2; ++px) {
            float4* acc = px ? acc1 : acc0;
            unsigned hi_u[8], lo_u[8];
#pragma unroll
            for (int gg = 0; gg < 4; ++gg) {
                float f[4] = { acc[gg].x, acc[gg].y, acc[gg].z, acc[gg].w };
#pragma unroll
                for (int e = 0; e < 2; ++e) {
                    float f0 = f[e * 2], f1 = f[e * 2 + 1];
                    __nv_bfloat16 h0 = __float2bfloat16(f0);
                    __nv_bfloat16 h1 = __float2bfloat16(f1);
                    __nv_bfloat16 l0 = __float2bfloat16(f0 - __bfloat162float(h0));
                    __nv_bfloat16 l1 = __float2bfloat16(f1 - __bfloat162float(h1));
                    hi_u[gg * 2 + e] = bfpack(h0, h1);
                    lo_u[gg * 2 + e] = bfpack(l0, l1);
                }
            }
            size_t ob = (px ? ob1 : ob0) + half * 16;
            *(uint4*)&g_ath[ob]     = make_uint4(hi_u[0], hi_u[1], hi_u[2], hi_u[3]);
            *(uint4*)&g_ath[ob + 8] = make_uint4(hi_u[4], hi_u[5], hi_u[6], hi_u[7]);
            *(uint4*)&g_atl[ob]     = make_uint4(lo_u[0], lo_u[1], lo_u[2], lo_u[3]);
            *(uint4*)&g_atl[ob + 8] = make_uint4(lo_u[4], lo_u[5], lo_u[6], lo_u[7]);
        }
    }
}

// ------------------------------------------------------------------
// Kernel 3: proj GEMM. A+B streamed per kt (ring-3), direct-STG
// epilogue. (R14 champion)
// ------------------------------------------------------------------
#define PBUF 40960
#define PSM  122880    // 3*40960

__device__ __forceinline__ void proj_issue(unsigned sb, int t, int bq, int hw0, int kt)
{
    const unsigned base = sb + (kt % 3) * PBUF;
    const int mrow = t >> 2, c4 = t & 3;
    unsigned ad = base + mrow * 80 + c4 * 16;
    size_t aoff = ((size_t)(bq * NH + kt) * HWSZ + hw0 + mrow) * HD + c4 * 8;
    cpa16(ad,         g_ath + aoff);
    cpa16(ad + 10240, g_atl + aoff);
    unsigned bd = base + 20480 + mrow * 80 + c4 * 16;
    size_t boff = (size_t)mrow * CH + kt * 32 + c4 * 8;
    cpa16(bd,         g_pwh + boff);
    cpa16(bd + 10240, g_pwl + boff);
}

__global__ __launch_bounds__(512) void proj_kernel(
    const float* __restrict__ pb, float* __restrict__ out)
{
    extern __shared__ __align__(16) char sm[];
    const unsigned sb = (unsigned)__cvta_generic_to_shared(sm);

    const int mtile = blockIdx.x;
    const int bq    = mtile / 98;
    const int hw0   = (mtile - bq * 98) * 128;
    const int t     = threadIdx.x;
    const int l     = t & 31, w = t >> 5;
    const int wm    = w >> 2, wn = w & 3;
    const int g     = l >> 3, i = l & 7;

    {
        proj_issue(sb, t, bq, hw0, 0);
        cpcommit();
        proj_issue(sb, t, bq, hw0, 1);
        cpcommit();
        cpwait1();
        __syncthreads();
    }

    float c[2][4][4];
#pragma unroll
    for (int mf = 0; mf < 2; ++mf)
#pragma unroll
        for (int nf = 0; nf < 4; ++nf)
#pragma unroll
            for (int r2 = 0; r2 < 4; ++r2) c[mf][nf][r2] = 0.f;

    for (int kt = 0; kt < 4; ++kt) {
        const unsigned Cb = sb + (kt % 3) * PBUF;
        if (kt < 2) { proj_issue(sb, t, bq, hw0, kt + 2); cpcommit(); }

#pragma unroll
        for (int kb = 0; kb < 32; kb += 16) {
            unsigned ah[2][4], al_[2][4], bh[4][2], bl[4][2];
#pragma unroll
            for (int mf = 0; mf < 2; ++mf) {
                int mrow = wm * 32 + mf * 16 + ((g & 1) << 3) + i;
                unsigned ad = Cb + mrow * 80 + kb * 2 + ((g >> 1) << 4);
                ldsm4(ah[mf], ad);
                ldsm4(al_[mf], ad + 10240);
            }
#pragma unroll
            for (int ng = 0; ng < 2; ++ng) {
                int nrow = wn * 32 + ng * 16 + ((g >> 1) << 3) + i;
                unsigned bd = Cb + 20480 + nrow * 80 + kb * 2 + ((g & 1) << 4);
                unsigned r[4];
                ldsm4(r, bd);
                bh[ng * 2][0] = r[0]; bh[ng * 2][1] = r[1];
                bh[ng * 2 + 1][0] = r[2]; bh[ng * 2 + 1][1] = r[3];
                ldsm4(r, bd + 10240);
                bl[ng * 2][0] = r[0]; bl[ng * 2][1] = r[1];
                bl[ng * 2 + 1][0] = r[2]; bl[ng * 2 + 1][1] = r[3];
            }
#pragma unroll
            for (int mf = 0; mf < 2; ++mf)
#pragma unroll
                for (int nf = 0; nf < 4; ++nf) {
                    mma16816(c[mf][nf], ah[mf], bh[nf]);
                    mma16816(c[mf][nf], ah[mf], bl[nf]);
                    mma16816(c[mf][nf], al_[mf], bh[nf]);
                }
        }
        if (kt < 2)       cpwait1();
        else if (kt == 2) cpwait0();
        __syncthreads();
    }

    // ---- direct STG epilogue: out[bq, n, hw0 + m] = c + pb[n] ----
#pragma unroll
    for (int mf = 0; mf < 2; ++mf)
#pragma unroll
        for (int nf = 0; nf < 4; ++nf) {
            int n = wn * 32 + nf * 8 + (l & 3) * 2;
            int m = wm * 32 + mf * 16 + (l >> 2);
            float b0 = pb[n], b1 = pb[n + 1];
            float* r0 = out + (size_t)(bq * CH + n) * HWSZ + hw0;
            float* r1 = out + (size_t)(bq * CH + n + 1) * HWSZ + hw0;
            r0[m]     = c[mf][nf][0] + b0;
            r1[m]     = c[mf][nf][1] + b1;
            r0[m + 8] = c[mf][nf][2] + b0;
            r1[m + 8] = c[mf][nf][3] + b1;
        }
}

// ------------------------------------------------------------------
extern "C" void kernel_launch(void* const* d_in, const int* in_sizes, int n_in,
                              void* d_out, int out_size)
{
    const float* x      = (const float*)d_in[0];
    const float* qkv_w  = (const float*)d_in[1];
    const float* qkv_b  = (const float*)d_in[2];
    const float* rpb    = (const float*)d_in[3];
    const float* proj_w = (const float*)d_in[4];
    const float* proj_b = (const float*)d_in[5];
    float* out = (float*)d_out;

    cudaFuncSetAttribute(qkvdot_kernel,
                         cudaFuncAttributeMaxDynamicSharedMemorySize, QSM);
    cudaFuncSetAttribute(proj_kernel,
                         cudaFuncAttributeMaxDynamicSharedMemorySize, PSM);

    split_w_kernel<<<(3 * CH * CH + CH * CH) / 1024, 256>>>(qkv_w, proj_w);
    qkvdot_kernel<<<784, 512, QSM>>>(x, qkv_b);
    attn_kernel<<<dim3(7, 7, 32), 128>>>(rpb);
    proj_kernel<<<784, 512, PSM>>>(proj_b, out);
}

// round 17
// speedup vs baseline: 1.0875x; 1.0114x over previous
#include <cuda_runtime.h>
#include <cuda_bf16.h>

#define BATCH 8
#define CH    128
#define HH    112
#define WW    112
#define HWSZ  12544     // 112*112
#define NH    4
#define HD    32
#define KS    7
#define KK2   49
#define SCALE 0.17677669529663687f   // 32^-0.5

// Persistent scratch (static device allocations).
static __device__ __align__(16) __nv_bfloat16 g_wqh[3*CH*CH];        // qkv_w hi, [n][k]
static __device__ __align__(16) __nv_bfloat16 g_wql[3*CH*CH];
static __device__ __align__(16) __nv_bfloat16 g_pwh[CH*CH];          // proj_w hi
static __device__ __align__(16) __nv_bfloat16 g_pwl[CH*CH];
static __device__ __align__(16) float g_v  [BATCH*NH*HWSZ*HD];       // (b,h,p,d)
static __device__ __align__(16) float g_dot[BATCH*NH*HWSZ];          // (b,h,p)
// att hi/lo in HEAD-BLOCKED layout (b,h,p,d): attn stores coalesce.
static __device__ __align__(16) __nv_bfloat16 g_ath[BATCH*NH*HWSZ*HD];
static __device__ __align__(16) __nv_bfloat16 g_atl[BATCH*NH*HWSZ*HD];

// ---------------- helpers ----------------------------------------

__device__ __forceinline__ unsigned bfpack(__nv_bfloat16 a, __nv_bfloat16 b) {
    return (unsigned)__bfloat16_as_ushort(a) | ((unsigned)__bfloat16_as_ushort(b) << 16);
}

__device__ __forceinline__ void split4(float4 v, uint2& hi, uint2& lo) {
    __nv_bfloat16 hx = __float2bfloat16(v.x);
    __nv_bfloat16 hy = __float2bfloat16(v.y);
    __nv_bfloat16 hz = __float2bfloat16(v.z);
    __nv_bfloat16 hw = __float2bfloat16(v.w);
    __nv_bfloat16 lx = __float2bfloat16(v.x - __bfloat162float(hx));
    __nv_bfloat16 ly = __float2bfloat16(v.y - __bfloat162float(hy));
    __nv_bfloat16 lz = __float2bfloat16(v.z - __bfloat162float(hz));
    __nv_bfloat16 lw = __float2bfloat16(v.w - __bfloat162float(hw));
    hi.x = bfpack(hx, hy); hi.y = bfpack(hz, hw);
    lo.x = bfpack(lx, ly); lo.y = bfpack(lz, lw);
}

__device__ __forceinline__ void ldsm4(unsigned* r, unsigned addr) {
    asm volatile("ldmatrix.sync.aligned.m8n8.x4.shared.b16 {%0,%1,%2,%3}, [%4];"
                 : "=r"(r[0]), "=r"(r[1]), "=r"(r[2]), "=r"(r[3]) : "r"(addr));
}
__device__ __forceinline__ void ldsm4t(unsigned* r, unsigned addr) {
    asm volatile("ldmatrix.sync.aligned.m8n8.x4.trans.shared.b16 {%0,%1,%2,%3}, [%4];"
                 : "=r"(r[0]), "=r"(r[1]), "=r"(r[2]), "=r"(r[3]) : "r"(addr));
}
__device__ __forceinline__ void mma16816(float* c, const unsigned* a, const unsigned* b) {
    asm volatile(
        "mma.sync.aligned.m16n8k16.row.col.f32.bf16.bf16.f32 "
        "{%0,%1,%2,%3}, {%4,%5,%6,%7}, {%8,%9}, {%0,%1,%2,%3};"
        : "+f"(c[0]), "+f"(c[1]), "+f"(c[2]), "+f"(c[3])
        : "r"(a[0]), "r"(a[1]), "r"(a[2]), "r"(a[3]), "r"(b[0]), "r"(b[1]));
}

__device__ __forceinline__ void cpa16(unsigned dst, const void* src) {
    asm volatile("cp.async.cg.shared.global [%0], [%1], 16;" :: "r"(dst), "l"(src));
}
__device__ __forceinline__ void cpcommit() { asm volatile("cp.async.commit_group;"); }
__device__ __forceinline__ void cpwait1()  { asm volatile("cp.async.wait_group 1;"); }
__device__ __forceinline__ void cpwait0()  { asm volatile("cp.async.wait_group 0;"); }

// ------------------------------------------------------------------
// Pre-split kernel: weights fp32 -> bf16 hi/lo (tiny)
// ------------------------------------------------------------------
__global__ __launch_bounds__(256) void split_w_kernel(
    const float* __restrict__ qw, const float* __restrict__ pw)
{
    int i = (blockIdx.x * 256 + threadIdx.x) * 4;
    uint2 hi, lo;
    if (i < 3 * CH * CH) {
        float4 v = *(const float4*)&qw[i];
        split4(v, hi, lo);
        *(uint2*)&g_wqh[i] = hi;
        *(uint2*)&g_wql[i] = lo;
    } else {
        int j = i - 3 * CH * CH;
        float4 v = *(const float4*)&pw[j];
        split4(v, hi, lo);
        *(uint2*)&g_pwh[j] = hi;
        *(uint2*)&g_pwl[j] = lo;
    }
}

// ------------------------------------------------------------------
// Kernel 1: fused QKV GEMM + q.k dot. bf16 3-term split.
// BK=64, 6 phases, 3-buffer cp.async ring. (R14 champion)
// ------------------------------------------------------------------
#define QA_H 0
#define QA_L 34816
#define QB0  69632
#define QBUF 36864
#define QSM  180224    // 69632 + 3*36864

__device__ __forceinline__ void qkv_issueB(unsigned sb, int t, int p)
{
    const int nt = p >> 1, ktH = p & 1, buf = p % 3;
    const int nrow = t >> 2, c4 = t & 3;
    unsigned bd = sb + QB0 + buf * QBUF + nrow * 144 + c4 * 32;
    size_t off = (size_t)(nt * 128 + nrow) * CH + ktH * 64 + c4 * 16;
    cpa16(bd,              g_wqh + off);
    cpa16(bd + 16,         g_wqh + off + 8);
    cpa16(bd + 18432,      g_wql + off);
    cpa16(bd + 18432 + 16, g_wql + off + 8);
}

__global__ __launch_bounds__(512) void qkvdot_kernel(
    const float* __restrict__ x, const float* __restrict__ bias)
{
    extern __shared__ __align__(16) char sm[];
    const unsigned sb = (unsigned)__cvta_generic_to_shared(sm);

    const int mtile = blockIdx.x;            // 0..783
    const int b     = mtile / 98;
    const int hw0   = (mtile - b * 98) * 128;
    const int t     = threadIdx.x;
    const int l     = t & 31, w = t >> 5;
    const int wm    = w >> 2, wn = w & 3;
    const int g     = l >> 3, i = l & 7;

    // ---- prologue: B(0), B(1) via cp.async; A fp32 load + split ----
    {
        qkv_issueB(sb, t, 0);
        cpcommit();
        qkv_issueB(sb, t, 1);
        cpcommit();

        const float* xb = x + (size_t)b * (CH * HWSZ) + hw0;
        const int m4 = (t & 31) * 4;
        const int kr = t >> 5;               // 0..15
        float4 av[8];
#pragma unroll
        for (int j = 0; j < 8; ++j)
            av[j] = *(const float4*)(xb + (size_t)(kr + j * 16) * HWSZ + m4);
#pragma unroll
        for (int j = 0; j < 8; ++j) {
            uint2 hi, lo;
            split4(av[j], hi, lo);
            unsigned ad = sb + QA_H + (kr + j * 16) * 272 + m4 * 2;
            *(uint2*)__cvta_shared_to_generic(ad) = hi;
            *(uint2*)__cvta_shared_to_generic(ad + (QA_L - QA_H)) = lo;
        }
        cpwait1();
        __syncthreads();
    }

    float c[2][4][4];
    float qreg[2][4][4];
#pragma unroll
    for (int mf = 0; mf < 2; ++mf)
#pragma unroll
        for (int nf = 0; nf < 4; ++nf)
#pragma unroll
            for (int r2 = 0; r2 < 4; ++r2) c[mf][nf][r2] = 0.f;

    for (int p = 0; p < 6; ++p) {
        const int nt = p >> 1, ktH = p & 1, buf = p % 3;

        if (p < 4) { qkv_issueB(sb, t, p + 2); cpcommit(); }

        const unsigned Bb = sb + QB0 + buf * QBUF;
#pragma unroll
        for (int kb = 0; kb < 64; kb += 16) {
            unsigned ah[2][4], al_[2][4], bh[4][2], bl[4][2];
#pragma unroll
            for (int mf = 0; mf < 2; ++mf) {
                int row  = ktH * 64 + kb + i + ((g >> 1) << 3);
                int mcol = wm * 32 + mf * 16 + ((g & 1) << 3);
                unsigned ad = sb + QA_H + row * 272 + mcol * 2;
                ldsm4t(ah[mf], ad);
                ldsm4t(al_[mf], ad + (QA_L - QA_H));
            }
#pragma unroll
            for (int ng = 0; ng < 2; ++ng) {
                int nrow = wn * 32 + ng * 16 + ((g >> 1) << 3) + i;
                unsigned bd = Bb + nrow * 144 + kb * 2 + ((g & 1) << 4);
                unsigned r[4];
                ldsm4(r, bd);
                bh[ng * 2][0] = r[0]; bh[ng * 2][1] = r[1];
                bh[ng * 2 + 1][0] = r[2]; bh[ng * 2 + 1][1] = r[3];
                ldsm4(r, bd + 18432);
                bl[ng * 2][0] = r[0]; bl[ng * 2][1] = r[1];
                bl[ng * 2 + 1][0] = r[2]; bl[ng * 2 + 1][1] = r[3];
            }
#pragma unroll
            for (int mf = 0; mf < 2; ++mf)
#pragma unroll
                for (int nf = 0; nf < 4; ++nf) {
                    mma16816(c[mf][nf], ah[mf], bh[nf]);
                    mma16816(c[mf][nf], ah[mf], bl[nf]);
                    mma16816(c[mf][nf], al_[mf], bh[nf]);
                }
        }

        if (ktH == 1) {
            if (nt == 0) {
#pragma unroll
                for (int mf = 0; mf < 2; ++mf)
#pragma unroll
                    for (int nf = 0; nf < 4; ++nf) {
                        int n = wn * 32 + nf * 8 + (l & 3) * 2;
                        float b0 = bias[n], b1 = bias[n + 1];
                        qreg[mf][nf][0] = c[mf][nf][0] + b0;
                        qreg[mf][nf][1] = c[mf][nf][1] + b1;
                        qreg[mf][nf][2] = c[mf][nf][2] + b0;
                        qreg[mf][nf][3] = c[mf][nf][3] + b1;
                    }
            } else if (nt == 1) {
#pragma unroll
                for (int mf = 0; mf < 2; ++mf) {
                    float s0 = 0.f, s1 = 0.f;
                    int m = wm * 32 + mf * 16 + (l >> 2);
#pragma unroll
                    for (int nf = 0; nf < 4; ++nf) {
                        int n = wn * 32 + nf * 8 + (l & 3) * 2;
                        float b0 = bias[128 + n], b1 = bias[128 + n + 1];
                        s0 += qreg[mf][nf][0] * (c[mf][nf][0] + b0)
                            + qreg[mf][nf][1] * (c[mf][nf][1] + b1);
                        s1 += qreg[mf][nf][2] * (c[mf][nf][2] + b0)
                            + qreg[mf][nf][3] * (c[mf][nf][3] + b1);
                    }
                    s0 += __shfl_xor_sync(0xffffffffu, s0, 1);
                    s0 += __shfl_xor_sync(0xffffffffu, s0, 2);
                    s1 += __shfl_xor_sync(0xffffffffu, s1, 1);
                    s1 += __shfl_xor_sync(0xffffffffu, s1, 2);
                    if ((l & 3) == 0) {
                        size_t base = (size_t)(b * NH + wn) * HWSZ + hw0;
                        g_dot[base + m]     = s0 * SCALE;
                        g_dot[base + m + 8] = s1 * SCALE;
                    }
                }
            } else {
#pragma unroll
                for (int mf = 0; mf < 2; ++mf)
#pragma unroll
                    for (int nf = 0; nf < 4; ++nf) {
                        int n = wn * 32 + nf * 8 + (l & 3) * 2;
                        int m = wm * 32 + mf * 16 + (l >> 2);
                        float b0 = bias[256 + n], b1 = bias[256 + n + 1];
                        int d = n & 31;
                        float* hb = g_v + ((size_t)(b * NH + wn) * HWSZ + hw0) * HD + d;
                        *(float2*)&hb[(size_t)m * HD] =
                            make_float2(c[mf][nf][0] + b0, c[mf][nf][1] + b1);
                        *(float2*)&hb[(size_t)(m + 8) * HD] =
                            make_float2(c[mf][nf][2] + b0, c[mf][nf][3] + b1);
                    }
            }
#pragma unroll
            for (int mf = 0; mf < 2; ++mf)
#pragma unroll
                for (int nf = 0; nf < 4; ++nf)
#pragma unroll
                    for (int r2 = 0; r2 < 4; ++r2) c[mf][nf][r2] = 0.f;
        }

        if (p < 4)       cpwait1();
        else if (p == 4) cpwait0();
        __syncthreads();
    }
}

// ------------------------------------------------------------------
// Kernel 2: neighborhood attention (circular), vertical 2-px strip.
// (R11/R14 champion — frozen)
// ------------------------------------------------------------------
__global__ __launch_bounds__(128) void attn_kernel(const float* __restrict__ rpb)
{
    __shared__ __align__(16) float ds[22 * 24];
    __shared__ __align__(16) float rs[KK2];
    __shared__ __align__(16) float vs[484 * 20];

    const int bh = blockIdx.z;        // b*4 + h
    const int h  = bh & 3;
    const int b  = bh >> 2;
    const int y0 = blockIdx.y * 16;
    const int x0 = blockIdx.x * 16;
    const int tid = threadIdx.x;

    for (int idx = tid; idx < 484; idx += 128) {
        int r  = idx / 22, cc = idx - r * 22;
        int gy = y0 + r;  if (gy >= HH) gy -= HH;
        int gx = x0 + cc; if (gx >= WW) gx -= WW;
        ds[r * 24 + cc] = g_dot[(size_t)bh * HWSZ + gy * WW + gx];
    }
    if (tid < KK2) rs[tid] = rpb[h * KK2 + tid];

    const float* vbase = g_v + (size_t)bh * (HWSZ * HD);

    for (int idx = tid; idx < 484 * 4; idx += 128) {
        int pix = idx >> 2, gg = idx & 3;
        int r  = pix / 22, cc = pix - r * 22;
        int gy = y0 + r;  if (gy >= HH) gy -= HH;
        int gx = x0 + cc; if (gx >= WW) gx -= WW;
        *(float4*)&vs[pix * 20 + gg * 4] =
            *(const float4*)&vbase[(size_t)(gy * WW + gx) * HD + gg * 4];
    }
    __syncthreads();

    const int ty2 = tid >> 4;          // 0..7 -> rows 2*ty2, 2*ty2+1
    const int tx  = tid & 15;

    float wgt[2][KK2];
#pragma unroll
    for (int px = 0; px < 2; ++px) {
        float mx = -1e30f;
#pragma unroll
        for (int i = 0; i < 7; ++i)
#pragma unroll
            for (int j = 0; j < 7; ++j) {
                float val = ds[(2 * ty2 + px + i) * 24 + tx + j] + rs[i * 7 + j];
                wgt[px][i * 7 + j] = val;
                mx = fmaxf(mx, val);
            }
        float sum = 0.f;
#pragma unroll
        for (int n = 0; n < KK2; ++n) { wgt[px][n] = __expf(wgt[px][n] - mx); sum += wgt[px][n]; }
        float inv = 1.f / sum;
#pragma unroll
        for (int n = 0; n < KK2; ++n) wgt[px][n] *= inv;
    }

    const int p0 = (y0 + 2 * ty2) * WW + (x0 + tx);
    const size_t ob0 = ((size_t)(b * NH + h) * HWSZ + p0) * HD;
    const size_t ob1 = ob0 + (size_t)WW * HD;

#pragma unroll
    for (int half = 0; half < 2; ++half) {
        if (half == 1) {
            __syncthreads();
            for (int idx = tid; idx < 484 * 4; idx += 128) {
                int pix = idx >> 2, gg = idx & 3;
                int r  = pix / 22, cc = pix - r * 22;
                int gy = y0 + r;  if (gy >= HH) gy -= HH;
                int gx = x0 + cc; if (gx >= WW) gx -= WW;
                *(float4*)&vs[pix * 20 + gg * 4] =
                    *(const float4*)&vbase[(size_t)(gy * WW + gx) * HD + 16 + gg * 4];
            }
            __syncthreads();
        }

        float4 acc0[4], acc1[4];
#pragma unroll
        for (int gg = 0; gg < 4; ++gg) {
            acc0[gg] = make_float4(0.f, 0.f, 0.f, 0.f);
            acc1[gg] = make_float4(0.f, 0.f, 0.f, 0.f);
        }
#pragma unroll
        for (int i = 0; i < 8; ++i)
#pragma unroll
            for (int j = 0; j < 7; ++j) {
                int pix = (2 * ty2 + i) * 22 + (tx + j);
                float w0 = (i < 7) ? wgt[0][i * 7 + j] : 0.f;
                float w1 = (i >= 1) ? wgt[1][(i - 1) * 7 + j] : 0.f;
#pragma unroll
                for (int gg = 0; gg < 4; ++gg) {
                    float4 vv = *(const float4*)&vs[pix * 20 + gg * 4];
                    if (i < 7) {
                        acc0[gg].x = fmaf(w0, vv.x, acc0[gg].x);
                        acc0[gg].y = fmaf(w0, vv.y, acc0[gg].y);
                        acc0[gg].z = fmaf(w0, vv.z, acc0[gg].z);
                        acc0[gg].w = fmaf(w0, vv.w, acc0[gg].w);
                    }
                    if (i >= 1) {
                        acc1[gg].x = fmaf(w1, vv.x, acc1[gg].x);
                        acc1[gg].y = fmaf(w1, vv.y, acc1[gg].y);
                        acc1[gg].z = fmaf(w1, vv.z, acc1[gg].z);
                        acc1[gg].w = fmaf(w1, vv.w, acc1[gg].w);
                    }
                }
            }

#pragma unroll
        for (int px = 0; px < 2; ++px) {
            float4* acc = px ? acc1 : acc0;
            unsigned hi_u[8], lo_u[8];
#pragma unroll
            for (int gg = 0; gg < 4; ++gg) {
                float f[4] = { acc[gg].x, acc[gg].y, acc[gg].z, acc[gg].w };
#pragma unroll
                for (int e = 0; e < 2; ++e) {
                    float f0 = f[e * 2], f1 = f[e * 2 + 1];
                    __nv_bfloat16 h0 = __float2bfloat16(f0);
                    __nv_bfloat16 h1 = __float2bfloat16(f1);
                    __nv_bfloat16 l0 = __float2bfloat16(f0 - __bfloat162float(h0));
                    __nv_bfloat16 l1 = __float2bfloat16(f1 - __bfloat162float(h1));
                    hi_u[gg * 2 + e] = bfpack(h0, h1);
                    lo_u[gg * 2 + e] = bfpack(l0, l1);
                }
            }
            size_t ob = (px ? ob1 : ob0) + half * 16;
            *(uint4*)&g_ath[ob]     = make_uint4(hi_u[0], hi_u[1], hi_u[2], hi_u[3]);
            *(uint4*)&g_ath[ob + 8] = make_uint4(hi_u[4], hi_u[5], hi_u[6], hi_u[7]);
            *(uint4*)&g_atl[ob]     = make_uint4(lo_u[0], lo_u[1], lo_u[2], lo_u[3]);
            *(uint4*)&g_atl[ob + 8] = make_uint4(lo_u[4], lo_u[5], lo_u[6], lo_u[7]);
        }
    }
}

// ------------------------------------------------------------------
// Kernel 3: proj GEMM, 256 threads / 2 CTA-per-SM variant.
// Same 128x128 tile; 8 warps (4m x 2n of 32x64); ring-2 chunks
// (2 x 40KB = 80KB -> 2 CTA/SM). B consumed in two ng-halves to
// bound live registers under the 128-reg 2-CTA limit.
// Direct-STG epilogue (R14-proven).
// ------------------------------------------------------------------
#define PBUF 40960
#define PSM  81920     // 2*40960

__device__ __forceinline__ void proj_issue(unsigned sb, int t, int bq, int hw0, int kt)
{
    const unsigned base = sb + (kt & 1) * PBUF;
    const int mrow = t >> 1, ch = (t & 1) * 2;
#pragma unroll
    for (int q = 0; q < 2; ++q) {
        int c4 = ch + q;
        unsigned ad = base + mrow * 80 + c4 * 16;
        size_t aoff = ((size_t)(bq * NH + kt) * HWSZ + hw0 + mrow) * HD + c4 * 8;
        cpa16(ad,         g_ath + aoff);
        cpa16(ad + 10240, g_atl + aoff);
        unsigned bd = base + 20480 + mrow * 80 + c4 * 16;
        size_t boff = (size_t)mrow * CH + kt * 32 + c4 * 8;
        cpa16(bd,         g_pwh + boff);
        cpa16(bd + 10240, g_pwl + boff);
    }
}

__global__ __launch_bounds__(256, 2) void proj_kernel(
    const float* __restrict__ pb, float* __restrict__ out)
{
    extern __shared__ __align__(16) char sm[];
    const unsigned sb = (unsigned)__cvta_generic_to_shared(sm);

    const int mtile = blockIdx.x;
    const int bq    = mtile / 98;
    const int hw0   = (mtile - bq * 98) * 128;
    const int t     = threadIdx.x;
    const int l     = t & 31, w = t >> 5;
    const int wm    = w & 3, wn = w >> 2;    // 4m x 2n; warp tile 32m x 64n
    const int g     = l >> 3, i = l & 7;

    {
        proj_issue(sb, t, bq, hw0, 0);
        cpcommit();
        proj_issue(sb, t, bq, hw0, 1);
        cpcommit();
        cpwait1();
        __syncthreads();
    }

    float c[2][8][4];
#pragma unroll
    for (int mf = 0; mf < 2; ++mf)
#pragma unroll
        for (int nf = 0; nf < 8; ++nf)
#pragma unroll
            for (int r2 = 0; r2 < 4; ++r2) c[mf][nf][r2] = 0.f;

    for (int kt = 0; kt < 4; ++kt) {
        const unsigned Cb = sb + (kt & 1) * PBUF;
#pragma unroll
        for (int kb = 0; kb < 32; kb += 16) {
            unsigned ah[2][4], al_[2][4];
#pragma unroll
            for (int mf = 0; mf < 2; ++mf) {
                int mrow = wm * 32 + mf * 16 + ((g & 1) << 3) + i;
                unsigned ad = Cb + mrow * 80 + kb * 2 + ((g >> 1) << 4);
                ldsm4(ah[mf], ad);
                ldsm4(al_[mf], ad + 10240);
            }
            // two ng-halves keep live B fragments bounded
#pragma unroll
            for (int nh2 = 0; nh2 < 2; ++nh2) {
                unsigned bh[4][2], bl[4][2];
#pragma unroll
                for (int ng = 0; ng < 2; ++ng) {
                    int nrow = wn * 64 + (nh2 * 2 + ng) * 16 + ((g >> 1) << 3) + i;
                    unsigned bd = Cb + 20480 + nrow * 80 + kb * 2 + ((g & 1) << 4);
                    unsigned r[4];
                    ldsm4(r, bd);
                    bh[ng * 2][0] = r[0]; bh[ng * 2][1] = r[1];
                    bh[ng * 2 + 1][0] = r[2]; bh[ng * 2 + 1][1] = r[3];
                    ldsm4(r, bd + 10240);
                    bl[ng * 2][0] = r[0]; bl[ng * 2][1] = r[1];
                    bl[ng * 2 + 1][0] = r[2]; bl[ng * 2 + 1][1] = r[3];
                }
#pragma unroll
                for (int mf = 0; mf < 2; ++mf)
#pragma unroll
                    for (int nf2 = 0; nf2 < 4; ++nf2) {
                        int nf = nh2 * 4 + nf2;
                        mma16816(c[mf][nf], ah[mf], bh[nf2]);
                        mma16816(c[mf][nf], ah[mf], bl[nf2]);
                        mma16816(c[mf][nf], al_[mf], bh[nf2]);
                    }
            }
        }
        // done reading buf kt&1 before overwriting it
        __syncthreads();
        if (kt < 2) { proj_issue(sb, t, bq, hw0, kt + 2); cpcommit(); }
        if (kt < 2)       cpwait1();
        else if (kt == 2) cpwait0();
        if (kt < 3) __syncthreads();
    }

    // ---- direct STG epilogue: out[bq, n, hw0 + m] = c + pb[n] ----
#pragma unroll
    for (int mf = 0; mf < 2; ++mf)
#pragma unroll
        for (int nf = 0; nf < 8; ++nf) {
            int n = wn * 64 + nf * 8 + (l & 3) * 2;
            int m = wm * 32 + mf * 16 + (l >> 2);
            float b0 = pb[n], b1 = pb[n + 1];
            float* r0 = out + (size_t)(bq * CH + n) * HWSZ + hw0;
            float* r1 = out + (size_t)(bq * CH + n + 1) * HWSZ + hw0;
            r0[m]     = c[mf][nf][0] + b0;
            r1[m]     = c[mf][nf][1] + b1;
            r0[m + 8] = c[mf][nf][2] + b0;
            r1[m + 8] = c[mf][nf][3] + b1;
        }
}

// ------------------------------------------------------------------
extern "C" void kernel_launch(void* const* d_in, const int* in_sizes, int n_in,
                              void* d_out, int out_size)
{
    const float* x      = (const float*)d_in[0];
    const float* qkv_w  = (const float*)d_in[1];
    const float* qkv_b  = (const float*)d_in[2];
    const float* rpb    = (const float*)d_in[3];
    const float* proj_w = (const float*)d_in[4];
    const float* proj_b = (const float*)d_in[5];
    float* out = (float*)d_out;

    cudaFuncSetAttribute(qkvdot_kernel,
                         cudaFuncAttributeMaxDynamicSharedMemorySize, QSM);
    cudaFuncSetAttribute(proj_kernel,
                         cudaFuncAttributeMaxDynamicSharedMemorySize, PSM);

    split_w_kernel<<<(3 * CH * CH + CH * CH) / 1024, 256>>>(qkv_w, proj_w);
    qkvdot_kernel<<<784, 512, QSM>>>(x, qkv_b);
    attn_kernel<<<dim3(7, 7, 32), 128>>>(rpb);
    proj_kernel<<<784, 256, PSM>>>(proj_b, out);
}